// round 16
// baseline (speedup 1.0000x reference)
#include <cuda_runtime.h>
#include <math.h>
#include <stdint.h>

typedef unsigned long long ull;

#define SEQ   1024
#define NTHR  256
#define NBLK  128          // 16 groups x 8 CTAs

// ---------------- device scratch (static allocs only) -----------------------
__device__ float    g_xq[(size_t)SEQ * 64 * 256 * 4];  // [t][b][u][gate]
__device__ float    g_hx[16][2][1024];                 // [group][buf][u*4 + b]
__device__ unsigned g_flag[(SEQ + 1) * 16 * 32];       // [t][group][rank, pad 32]

// ---------------- f32x2 packed helpers (Blackwell) --------------------------
__device__ __forceinline__ ull fma2(ull a, ull b, ull c) {
    ull d;
    asm("fma.rn.f32x2 %0, %1, %2, %3;" : "=l"(d) : "l"(a), "l"(b), "l"(c));
    return d;
}
__device__ __forceinline__ ull add2(ull a, ull b) {
    ull d;
    asm("add.rn.f32x2 %0, %1, %2;" : "=l"(d) : "l"(a), "l"(b));
    return d;
}
__device__ __forceinline__ ull pack2(float x, float y) {
    ull r;
    asm("mov.b64 %0, {%1, %2};" : "=l"(r) : "f"(x), "f"(y));
    return r;
}
__device__ __forceinline__ float2 unpack2(ull v) {
    float2 r;
    asm("mov.b64 {%0, %1}, %2;" : "=f"(r.x), "=f"(r.y) : "l"(v));
    return r;
}
__device__ __forceinline__ float4 ldcg_f4(const float* p) {
    float4 v;
    asm volatile("ld.global.cg.v4.f32 {%0, %1, %2, %3}, [%4];"
                 : "=f"(v.x), "=f"(v.y), "=f"(v.z), "=f"(v.w) : "l"(p));
    return v;
}
__device__ __forceinline__ unsigned ld_acq(const unsigned* p) {
    unsigned v;
    asm volatile("ld.acquire.gpu.global.u32 %0, [%1];" : "=r"(v) : "l"(p));
    return v;
}
__device__ __forceinline__ void st_rel(unsigned* p, unsigned v) {
    asm volatile("st.release.gpu.global.u32 [%0], %1;" :: "l"(p), "r"(v) : "memory");
}
__device__ __forceinline__ float ftanh(float x) {     // 1 - 2/(e^{2x}+1)
    float e = __expf(2.0f * x);
    return 1.0f - 2.0f / (e + 1.0f);
}
__device__ __forceinline__ float fsigmoid(float x) {
    return 1.0f / (1.0f + __expf(-x));
}

// ======================= Phase 1: X projection GEMM =========================
// g_xq[t][b][u][g] = sum_k X[t,b,k] * W_g[k][u] + bias_g[u]
// block bx = 16-unit block (all 4 gates), 64 cols c = u_l*4 + g
__global__ __launch_bounds__(256) void xproj_kernel(
    const float* __restrict__ X,
    const float* __restrict__ Wf, const float* __restrict__ Wi,
    const float* __restrict__ Wg, const float* __restrict__ Wo,
    const float* __restrict__ bf, const float* __restrict__ bi,
    const float* __restrict__ bg, const float* __restrict__ bo)
{
    __shared__ float As[16 * 68];   // [k][row]
    __shared__ float Bs[16 * 68];   // [k][c], c = u_l*4 + g

    const int t  = blockIdx.y;
    const int bx = blockIdx.x;      // unit block 0..15
    const int tx = threadIdx.x;

    // re-zero flags every replay (xproj completes before lstm starts)
    if (bx == 0) {
        for (int i = tx; i < 512; i += 256) g_flag[((size_t)t << 9) + i] = 0u;
        if (t == 0)
            for (int i = tx; i < 512; i += 256) g_flag[((size_t)SEQ << 9) + i] = 0u;
    }

    const int trow4 = (tx >> 4) * 4;       // batch rows
    const int tcol4 = (tx & 15) * 4;       // cols (one unit, 4 gates)

    // A loader
    const int arow = tx >> 2;
    const int akq  = (tx & 3) * 4;
    // B loader: (bk = k-in-tile, bu = unit-in-block)
    const int bk = tx >> 4;
    const int bu = tx & 15;
    const int Jb = (bx << 4) + bu;

    const float* Aptr = X + ((size_t)t * 64 + arow) * 256 + akq;

    ull acc[8];
    #pragma unroll
    for (int i = 0; i < 8; ++i) acc[i] = 0ull;

    float4 aReg = *(const float4*)Aptr;
    float wfR = Wf[bk * 256 + Jb];
    float wiR = Wi[bk * 256 + Jb];
    float wgR = Wg[bk * 256 + Jb];
    float woR = Wo[bk * 256 + Jb];

    for (int kt = 0; kt < 16; ++kt) {
        __syncthreads();
        As[(akq + 0) * 68 + arow] = aReg.x;
        As[(akq + 1) * 68 + arow] = aReg.y;
        As[(akq + 2) * 68 + arow] = aReg.z;
        As[(akq + 3) * 68 + arow] = aReg.w;
        *(float4*)&Bs[bk * 68 + (bu << 2)] = make_float4(wfR, wiR, wgR, woR);
        if (kt < 15) {
            aReg = *(const float4*)(Aptr + (kt + 1) * 16);
            int off = (kt + 1) * 16 * 256 + bk * 256 + Jb;
            wfR = Wf[off]; wiR = Wi[off]; wgR = Wg[off]; woR = Wo[off];
        }
        __syncthreads();

        #pragma unroll
        for (int k = 0; k < 16; ++k) {
            float4 a4 = *(const float4*)&As[k * 68 + trow4];
            float4 b4 = *(const float4*)&Bs[k * 68 + tcol4];
            ull a01 = pack2(a4.x, a4.y);
            ull a23 = pack2(a4.z, a4.w);
            ull bb;
            bb = pack2(b4.x, b4.x); acc[0] = fma2(a01, bb, acc[0]); acc[1] = fma2(a23, bb, acc[1]);
            bb = pack2(b4.y, b4.y); acc[2] = fma2(a01, bb, acc[2]); acc[3] = fma2(a23, bb, acc[3]);
            bb = pack2(b4.z, b4.z); acc[4] = fma2(a01, bb, acc[4]); acc[5] = fma2(a23, bb, acc[5]);
            bb = pack2(b4.w, b4.w); acc[6] = fma2(a01, bb, acc[6]); acc[7] = fma2(a23, bb, acc[7]);
        }
    }

    // epilogue: rows = batches trow4..+3, cols = gates 0..3 of unit J
    const int J = (bx << 4) + (tcol4 >> 2);
    const float4 bv = make_float4(bf[J], bi[J], bg[J], bo[J]);
    float2 c0 = unpack2(acc[0]), c1 = unpack2(acc[2]), c2 = unpack2(acc[4]), c3 = unpack2(acc[6]);
    float2 d0 = unpack2(acc[1]), d1 = unpack2(acc[3]), d2 = unpack2(acc[5]), d3 = unpack2(acc[7]);
    float4 o0 = make_float4(c0.x + bv.x, c1.x + bv.y, c2.x + bv.z, c3.x + bv.w);
    float4 o1 = make_float4(c0.y + bv.x, c1.y + bv.y, c2.y + bv.z, c3.y + bv.w);
    float4 o2 = make_float4(d0.x + bv.x, d1.x + bv.y, d2.x + bv.z, d3.x + bv.w);
    float4 o3 = make_float4(d0.y + bv.x, d1.y + bv.y, d2.y + bv.z, d3.y + bv.w);
    size_t base = (((size_t)t * 64 + trow4) * 256 + J) * 4;   // float index
    *(float4*)&g_xq[base         ] = o0;
    *(float4*)&g_xq[base + 1024  ] = o1;
    *(float4*)&g_xq[base + 2048  ] = o2;
    *(float4*)&g_xq[base + 3072  ] = o3;
}

// ======================= Phase 2: persistent recurrence =====================
// 16 INDEPENDENT groups of 8 CTAs. Group q owns batches [4q,4q+4); CTA rank r
// owns units [32r,32r+32) x 4 gates (weights resident in smem, 130KB).
// Per step: poll 8 flags (one 32B sector), load group's h (4KB, L2), dup into
// smem, matvec (no reduce), gates->smem, update (c in regs), store 512B h,
// release. Groups never synchronize with each other.
__global__ __launch_bounds__(NTHR, 1) void lstm_seq_kernel(
    const float* __restrict__ Wf, const float* __restrict__ Wi,
    const float* __restrict__ Wg, const float* __restrict__ Wo,
    float* __restrict__ out)
{
    extern __shared__ ull smx[];
    ull* wsm = smx;            // [cp][k] pairs, stride 258 : 16512 ull (129KB)
    ull* hd  = wsm + 16512;    // [b][k] dup pairs, stride 260 : 1040 ull
    ull* gsm = hd + 1040;      // [b*32+u][j] : 256 ull
    // total 17808 ull = 142,464 B

    const int tx = threadIdx.x;
    const int q  = blockIdx.x >> 3;      // group
    const int r  = blockIdx.x & 7;       // rank in group

    // GEMM roles: warp owns 8 colpairs; lane = b*8 + cpl
    const int lane = tx & 31;
    const int b    = lane >> 3;                    // batch 0..3 (local)
    const int cp   = ((tx >> 5) << 3) + (lane & 7); // colpair 0..63
    const int u    = cp >> 1;                      // unit 0..31 (local)
    const int j    = cp & 1;                       // gate pair: 0=(f,i) 1=(g,o)

    // ---- fill weight smem: wsm[cp][k] = (W_{2j}[256+k][U], W_{2j+1}[256+k][U])
    for (int idx = tx; idx < 16384; idx += NTHR) {
        int k = idx >> 6, cpq = idx & 63;
        int uu = cpq >> 1, jj = cpq & 1;
        int U = (r << 5) + uu;
        const float* Wa = jj ? Wg : Wf;
        const float* Wb = jj ? Wo : Wi;
        wsm[cpq * 258 + k] = pack2(Wa[(size_t)(256 + k) * 256 + U],
                                   Wb[(size_t)(256 + k) * 256 + U]);
    }

    // ---- init: h(0)=0 (my slice), c=0 in register ----
    float c_reg = 0.0f;
    if (tx < 128) g_hx[q][0][(r << 7) + tx] = 0.0f;
    __syncthreads();
    if (tx == 0) st_rel(&g_flag[(q << 5) + r], 1u);

    float* outs = out;
    float* hxo  = out + (size_t)SEQ * 64 * 256;
    float* cxo  = hxo + 64 * 256;

    const ull* wp = wsm + cp * 258;
    const ull* hp = hd + b * 260;
    const size_t xq_idx = ((((size_t)(q << 2) + b) << 8) + (r << 5) + u) * 4 + (j << 1);

    for (int t = 0; t < SEQ; ++t) {
        // prefetch x-projection pair (gates 2j,2j+1 of unit u, batch b)
        ull xq = *(const ull*)&g_xq[(size_t)t * 65536 + xq_idx];

        // poll my group's 8 flags: lanes 0-7, one 32B sector, all-vote
        {
            const unsigned* fp = &g_flag[((size_t)t << 9) + (q << 5) + (lane & 7)];
            unsigned v = ld_acq(fp);
            while (!__all_sync(0xffffffffu, (lane >= 8) | (v != 0u))) {
                __nanosleep(20);
                v = ld_acq(fp);
            }
        }

        // load group's h (4KB from L2), duplicate into smem pairs hd[b][k]
        {
            float4 hv = ldcg_f4(&g_hx[q][t & 1][tx << 2]);   // unit tx, batches 0..3
            hd[tx]       = pack2(hv.x, hv.x);
            hd[260 + tx] = pack2(hv.y, hv.y);
            hd[520 + tx] = pack2(hv.z, hv.z);
            hd[780 + tx] = pack2(hv.w, hv.w);
        }
        __syncthreads();

        // ---- matvec: preact pair += sum_k h[k][b] * (w2j, w2j+1)[k][u] ----
        ull acc0 = xq, acc1 = 0ull;
        #pragma unroll 16
        for (int k = 0; k < 256; k += 2) {
            ulonglong2 hh = *(const ulonglong2*)(hp + k);
            ulonglong2 ww = *(const ulonglong2*)(wp + k);
            acc0 = fma2(hh.x, ww.x, acc0);
            acc1 = fma2(hh.y, ww.y, acc1);
        }
        ull acc = add2(acc0, acc1);

        // activation (j=0: sigmoid,sigmoid ; j=1: tanh,sigmoid) -> gsm
        {
            float2 pv = unpack2(acc);
            float ax, ay;
            if (j == 0) { ax = fsigmoid(pv.x); ay = fsigmoid(pv.y); }
            else        { ax = ftanh(pv.x);    ay = fsigmoid(pv.y); }
            gsm[(((b << 5) + u) << 1) + j] = pack2(ax, ay);
        }
        __syncthreads();

        // ---- update: thread (u_l = tx>>2, b_l = tx&3), c in register ----
        if (tx < 128) {
            int u_l = tx >> 2, b_l = tx & 3;
            ulonglong2 e = *(const ulonglong2*)&gsm[((b_l << 5) + u_l) << 1];
            float2 fi = unpack2(e.x);     // (f, i)
            float2 go = unpack2(e.y);     // (g, o)
            c_reg = fi.x * c_reg + fi.y * go.x;
            float h = go.y * ftanh(c_reg);
            g_hx[q][(t + 1) & 1][(r << 7) + tx] = h;
            asm volatile("bar.sync 1, 128;" ::: "memory");   // warps 0-3 only
            if (tx == 0) st_rel(&g_flag[(((size_t)(t + 1)) << 9) + (q << 5) + r], 1u);
            int B = (q << 2) + b_l, U = (r << 5) + u_l;
            outs[((size_t)t * 64 + B) * 256 + U] = h;
            if (t == SEQ - 1) {
                hxo[B * 256 + U] = h;
                cxo[B * 256 + U] = c_reg;
            }
        }
        // warps 4-7 run ahead to next poll; hd/gsm reuse hazards are covered
        // by the flag chain (flags(t+1) imply ALL group CTAs passed this
        // step's __syncthreads pair) and the two full syncs above.
    }
}

// ============================== launch ======================================
extern "C" void kernel_launch(void* const* d_in, const int* in_sizes, int n_in,
                              void* d_out, int out_size)
{
    (void)in_sizes; (void)n_in; (void)out_size;
    const float* X  = (const float*)d_in[0];
    const float* Wf = (const float*)d_in[1];
    const float* bf = (const float*)d_in[2];
    const float* Wi = (const float*)d_in[3];
    const float* bi = (const float*)d_in[4];
    const float* Wg = (const float*)d_in[5];
    const float* bg = (const float*)d_in[6];
    const float* Wo = (const float*)d_in[7];
    const float* bo = (const float*)d_in[8];
    float* out = (float*)d_out;

    dim3 g1(16, 1024);
    xproj_kernel<<<g1, 256>>>(X, Wf, Wi, Wg, Wo, bf, bi, bg, bo);

    const int smem2 = 17808 * 8;   // 142,464 B
    cudaFuncSetAttribute(lstm_seq_kernel,
                         cudaFuncAttributeMaxDynamicSharedMemorySize, smem2);
    lstm_seq_kernel<<<NBLK, NTHR, smem2>>>(Wf, Wi, Wg, Wo, out);
}